// round 12
// baseline (speedup 1.0000x reference)
#include <cuda_runtime.h>
#include <cuda_bf16.h>
#include <cuda_fp16.h>
#include <cstdint>

#define NTOK 16384
#define DIN  512
#define NB   8
#define KR   4608                 // K = 512*9, single fp16 term
#define BK   64                   // K per stage = 128 bytes/row
#define NST  72                   // KR / BK (divisible by 4)
#define STAGE_BYTES 49152         // A 32KB + B 16KB
#define CTA_M 256
#define CTA_N 128

// Scratch (allocation-free), fp16 payloads
__device__ __align__(16) unsigned short g_F[(size_t)NTOK * KR];
__device__ __align__(16) unsigned short g_W[(size_t)512 * KR];

__device__ __forceinline__ void cpa16(uint32_t dst, const void* src) {
    asm volatile("cp.async.cg.shared.global [%0], [%1], 16;" :: "r"(dst), "l"(src));
}
__device__ __forceinline__ void ldsm_x4(uint32_t* r, uint32_t addr) {
    asm volatile("ldmatrix.sync.aligned.m8n8.x4.shared.b16 {%0,%1,%2,%3}, [%4];"
                 : "=r"(r[0]), "=r"(r[1]), "=r"(r[2]), "=r"(r[3]) : "r"(addr));
}
__device__ __forceinline__ void mma_f16_f32(float* c, const uint32_t* a,
                                            uint32_t b0, uint32_t b1) {
    asm volatile("mma.sync.aligned.m16n8k16.row.col.f32.f16.f16.f32 "
                 "{%0,%1,%2,%3}, {%4,%5,%6,%7}, {%8,%9}, {%0,%1,%2,%3};"
                 : "+f"(c[0]), "+f"(c[1]), "+f"(c[2]), "+f"(c[3])
                 : "r"(a[0]), "r"(a[1]), "r"(a[2]), "r"(a[3]), "r"(b0), "r"(b1));
}

// dummy: keeps gemm_kernel at launch index 3 (the ncu capture slot)
__global__ void shift_kernel() {}

// ---------------------------------------------------------------------------
// Kernel 1: LayerNorm + features -> fp16 A [tok][j*512+d]
// ---------------------------------------------------------------------------
__global__ __launch_bounds__(512)
void feat_kernel(const float* __restrict__ x,
                 const float* __restrict__ gamma_,
                 const float* __restrict__ beta_)
{
    const int tok = blockIdx.x;
    const int d   = threadIdx.x;
    const float v = x[(size_t)tok * DIN + d];

    __shared__ float red1[16], red2[16];

    float s1 = v, s2 = v * v;
    #pragma unroll
    for (int o = 16; o > 0; o >>= 1) {
        s1 += __shfl_xor_sync(0xffffffffu, s1, o);
        s2 += __shfl_xor_sync(0xffffffffu, s2, o);
    }
    if ((d & 31) == 0) { red1[d >> 5] = s1; red2[d >> 5] = s2; }
    __syncthreads();
    if (d < 16) {
        float t1 = red1[d], t2 = red2[d];
        #pragma unroll
        for (int o = 8; o > 0; o >>= 1) {
            t1 += __shfl_xor_sync(0x0000ffffu, t1, o);
            t2 += __shfl_xor_sync(0x0000ffffu, t2, o);
        }
        if (d == 0) { red1[0] = t1; red2[0] = t2; }
    }
    __syncthreads();
    const float mu  = red1[0] * (1.0f / DIN);
    const float var = red2[0] * (1.0f / DIN) - mu * mu;
    const float xn  = (v - mu) * rsqrtf(var + 1e-5f) * gamma_[d] + beta_[d];

    // cubic B-spline via closed-form symmetric kernel
    const float p = (xn + 3.3f) * (1.0f / 0.6f);
    float b[8];
    #pragma unroll
    for (int j = 0; j < 8; j++) {
        const float r  = fabsf(p - (float)(j + 2));
        const float t2 = fmaxf(2.0f - r, 0.0f);
        const float t1 = fmaxf(1.0f - r, 0.0f);
        b[j] = (t2 * t2 * t2 - 4.0f * t1 * t1 * t1) * (1.0f / 6.0f);
    }

    // RBF via two-sided exp-ratio chains (4 expf)
    const float xh = (xn + 1.5f) * (7.0f / 3.0f);
    const float C2 = 0.13533528f;   // e^-2
    float rb[8];
    {
        float gl = __expf(-xh * xh);
        float fl = __expf(2.0f * xh - 1.0f);
        #pragma unroll
        for (int j = 0; j < 8; j++) { rb[j] = gl; gl *= fl; fl *= C2; }
        float gr = __expf(-(xh - 7.0f) * (xh - 7.0f));
        float fr = __expf(13.0f - 2.0f * xh);
        #pragma unroll
        for (int j = 7; j >= 0; j--) { rb[j] = fmaxf(rb[j], gr); gr *= fr; fr *= C2; }
    }

    unsigned short* row = g_F + (size_t)tok * KR;
    row[d] = __half_as_ushort(__float2half_rn(fmaxf(xn, 0.0f)));
    #pragma unroll
    for (int j = 0; j < NB; j++)
        row[(1 + j) * 512 + d] = __half_as_ushort(__float2half_rn(b[j] + rb[j]));
}

// ---------------------------------------------------------------------------
// Kernel 2: pack weights -> fp16 B [o][j*512+d]
// ---------------------------------------------------------------------------
__global__ void pack_kernel(const float* __restrict__ bw,
                            const float* __restrict__ sw)
{
    const int idx = blockIdx.x * blockDim.x + threadIdx.x;
    if (idx >= 512 * KR) return;
    const int o = idx / KR;
    const int k = idx % KR;
    const int j = k >> 9;
    const int d = k & 511;
    const float w = (j == 0) ? bw[(size_t)o * DIN + d]
                             : sw[(size_t)o * (DIN * NB) + d * NB + (j - 1)];
    g_W[idx] = __half_as_ushort(__float2half_rn(w));
}

// ---------------------------------------------------------------------------
// Kernel 3: fp16 mma.sync GEMM  C[16384][512] = A[16384][4608] * B^T
// CTA 256x128, 8 warps (4M x 2N) of 64x64 tiles, BK=64 SW128, 4-stage
// cp.async pipeline, frag double-buffer (R7-proven structure).
// ---------------------------------------------------------------------------
__global__ __launch_bounds__(256, 1)
void gemm_kernel(float* __restrict__ C)
{
    extern __shared__ char smem_raw[];
    uint32_t raw;
    asm("{ .reg .u64 t; cvta.to.shared.u64 t, %1; cvt.u32.u64 %0, t; }"
        : "=r"(raw) : "l"(smem_raw));
    const uint32_t base = (raw + 1023) & ~1023u;

    const int tid  = threadIdx.x;
    const int wid  = tid >> 5;
    const int lane = tid & 31;
    const int wm   = wid & 3;          // 0..3 along M (64 each)
    const int wn   = wid >> 2;         // 0..1 along N (64 each)
    const int bm   = blockIdx.y * CTA_M;
    const int bn   = blockIdx.x * CTA_N;

    const int ld_r0 = tid >> 3;        // 0..31
    const int ld_c  = tid & 7;

    const int rx  = lane & 7;
    const int hiA = lane >> 4;
    const int hiB = (lane >> 3) & 1;
    uint32_t aoff[4], boff[4];
    #pragma unroll
    for (int mt = 0; mt < 4; mt++)
        aoff[mt] = (uint32_t)(wm * 64 + mt * 16 + (lane & 15)) * 128u;
    #pragma unroll
    for (int p = 0; p < 4; p++)
        boff[p] = 32768u + (uint32_t)(wn * 64 + p * 16 + (lane & 7) + ((lane >> 4) << 3)) * 128u;

    float acc[4][8][4];
    #pragma unroll
    for (int mt = 0; mt < 4; mt++)
        #pragma unroll
        for (int nt = 0; nt < 8; nt++)
            #pragma unroll
            for (int q = 0; q < 4; q++) acc[mt][nt][q] = 0.0f;

    uint32_t fa[2][4][4], fb[2][4][4];

    #define LOAD_STAGE(sidx, SBASE) do {                                        \
        const int ko_ = (sidx) * BK;                                            \
        _Pragma("unroll")                                                       \
        for (int i_ = 0; i_ < 8; i_++) {                                        \
            const int r_ = ld_r0 + i_ * 32;                                     \
            cpa16((SBASE) + r_ * 128 + ((ld_c ^ (r_ & 7)) << 4),                \
                  g_F + (size_t)(bm + r_) * KR + ko_ + ld_c * 8);               \
        }                                                                       \
        _Pragma("unroll")                                                       \
        for (int i_ = 0; i_ < 4; i_++) {                                        \
            const int r_ = ld_r0 + i_ * 32;                                     \
            cpa16((SBASE) + 32768u + r_ * 128 + ((ld_c ^ (r_ & 7)) << 4),       \
                  g_W + (size_t)(bn + r_) * KR + ko_ + ld_c * 8);               \
        }                                                                       \
    } while (0)

    #define LOAD_FRAGS(SBASE, ks_, A_, B_) do {                                 \
        _Pragma("unroll")                                                       \
        for (int mt_ = 0; mt_ < 4; mt_++)                                       \
            ldsm_x4((A_)[mt_], (SBASE) + aoff[mt_] +                            \
                    ((uint32_t)((((ks_) << 1) | hiA) ^ rx) << 4));              \
        _Pragma("unroll")                                                       \
        for (int p_ = 0; p_ < 4; p_++)                                          \
            ldsm_x4((B_)[p_], (SBASE) + boff[p_] +                              \
                    ((uint32_t)((((ks_) << 1) | hiB) ^ rx) << 4));              \
    } while (0)

    #define MMA_ALL(A_, B_) do {                                                \
        _Pragma("unroll")                                                       \
        for (int mt_ = 0; mt_ < 4; mt_++)                                       \
            _Pragma("unroll")                                                   \
            for (int nt_ = 0; nt_ < 8; nt_++) {                                 \
                const uint32_t b0_ = (nt_ & 1) ? (B_)[nt_ >> 1][2] : (B_)[nt_ >> 1][0]; \
                const uint32_t b1_ = (nt_ & 1) ? (B_)[nt_ >> 1][3] : (B_)[nt_ >> 1][1]; \
                mma_f16_f32(acc[mt_][nt_], (A_)[mt_], b0_, b1_);                \
            }                                                                   \
    } while (0)

    #define STEP(sv, BUF) do {                                                  \
        const int s_ = (sv);                                                    \
        asm volatile("cp.async.wait_group 2;" ::: "memory");                    \
        __syncthreads();                                                        \
        const uint32_t SA_ = base + (uint32_t)(BUF) * STAGE_BYTES;              \
        LOAD_FRAGS(SA_, 0, fa[0], fb[0]);                                       \
        if (s_ + 3 < NST) {                                                     \
            LOAD_STAGE(s_ + 3, base + (uint32_t)(((BUF) + 3) & 3) * STAGE_BYTES); \
        }                                                                       \
        asm volatile("cp.async.commit_group;" ::: "memory");                    \
        _Pragma("unroll")                                                       \
        for (int ks_ = 0; ks_ < 4; ks_++) {                                     \
            const int cur_ = ks_ & 1;                                           \
            if (ks_ < 3) LOAD_FRAGS(SA_, ks_ + 1, fa[cur_ ^ 1], fb[cur_ ^ 1]);  \
            MMA_ALL(fa[cur_], fb[cur_]);                                        \
        }                                                                       \
    } while (0)

    // prologue: stages 0..2 into bufs 0..2
    LOAD_STAGE(0, base);
    asm volatile("cp.async.commit_group;" ::: "memory");
    LOAD_STAGE(1, base + STAGE_BYTES);
    asm volatile("cp.async.commit_group;" ::: "memory");
    LOAD_STAGE(2, base + 2 * STAGE_BYTES);
    asm volatile("cp.async.commit_group;" ::: "memory");

    for (int t = 0; t < NST; t += 4) {
        STEP(t + 0, 0);
        STEP(t + 1, 1);
        STEP(t + 2, 2);
        STEP(t + 3, 3);
    }

    // epilogue: thread holds rows g, g+8 and cols 2tg, 2tg+1 per (mt, nt)
    const int g  = lane >> 2;
    const int tg = lane & 3;
    #pragma unroll
    for (int mt = 0; mt < 4; mt++) {
        const int row0 = bm + wm * 64 + mt * 16 + g;
        #pragma unroll
        for (int nt = 0; nt < 8; nt++) {
            const int col = bn + wn * 64 + nt * 8 + tg * 2;
            float2 v0; v0.x = acc[mt][nt][0]; v0.y = acc[mt][nt][1];
            float2 v1; v1.x = acc[mt][nt][2]; v1.y = acc[mt][nt][3];
            *(float2*)&C[(size_t)row0 * 512 + col]       = v0;
            *(float2*)&C[(size_t)(row0 + 8) * 512 + col] = v1;
        }
    }
}

// ---------------------------------------------------------------------------
extern "C" void kernel_launch(void* const* d_in, const int* in_sizes, int n_in,
                              void* d_out, int out_size)
{
    const float* x  = (const float*)d_in[0];
    const float* g  = (const float*)d_in[1];
    const float* bt = (const float*)d_in[2];
    const float* bw = (const float*)d_in[3];
    const float* sw = (const float*)d_in[4];
    float* out = (float*)d_out;

    const int SMEM_DYN = 1024 + 4 * STAGE_BYTES;
    cudaFuncSetAttribute(gemm_kernel, cudaFuncAttributeMaxDynamicSharedMemorySize, SMEM_DYN);

    shift_kernel<<<1, 32>>>();                     // idx 0
    feat_kernel<<<NTOK, 512>>>(x, g, bt);          // idx 1
    pack_kernel<<<(512 * KR + 255) / 256, 256>>>(bw, sw);  // idx 2
    gemm_kernel<<<dim3(512 / CTA_N, NTOK / CTA_M), 256, SMEM_DYN>>>(out);  // idx 3
}

// round 13
// speedup vs baseline: 1.4408x; 1.4408x over previous
#include <cuda_runtime.h>
#include <cuda_bf16.h>
#include <cuda_fp16.h>
#include <cstdint>

#define NTOK 16384
#define DIN  512
#define NB   8
#define KR   4608                 // K = 512*9, single fp16 term
#define BK   64                   // K per stage = 128 bytes/row
#define NST  72                   // KR / BK (divisible by 4)
#define STAGE_BYTES 49152         // A 32KB + B 16KB
#define CTA_M 256
#define CTA_N 128

// Scratch (allocation-free), fp16 payloads
__device__ __align__(16) unsigned short g_F[(size_t)NTOK * KR];
__device__ __align__(16) unsigned short g_W[(size_t)512 * KR];

__device__ __forceinline__ void cpa16(uint32_t dst, const void* src) {
    asm volatile("cp.async.cg.shared.global [%0], [%1], 16;" :: "r"(dst), "l"(src));
}
__device__ __forceinline__ void ldsm_x4(uint32_t* r, uint32_t addr) {
    asm volatile("ldmatrix.sync.aligned.m8n8.x4.shared.b16 {%0,%1,%2,%3}, [%4];"
                 : "=r"(r[0]), "=r"(r[1]), "=r"(r[2]), "=r"(r[3]) : "r"(addr));
}
__device__ __forceinline__ void mma_f16_f32(float* c, const uint32_t* a,
                                            uint32_t b0, uint32_t b1) {
    asm volatile("mma.sync.aligned.m16n8k16.row.col.f32.f16.f16.f32 "
                 "{%0,%1,%2,%3}, {%4,%5,%6,%7}, {%8,%9}, {%0,%1,%2,%3};"
                 : "+f"(c[0]), "+f"(c[1]), "+f"(c[2]), "+f"(c[3])
                 : "r"(a[0]), "r"(a[1]), "r"(a[2]), "r"(a[3]), "r"(b0), "r"(b1));
}

// ---------------------------------------------------------------------------
// per-dim feature vector from normalized activation xn
// ---------------------------------------------------------------------------
__device__ __forceinline__ void features_of(float xn, float* feat) {
    // cubic B-spline via closed-form symmetric kernel
    const float p = (xn + 3.3f) * (1.0f / 0.6f);
    float b[8];
    #pragma unroll
    for (int j = 0; j < 8; j++) {
        const float r  = fabsf(p - (float)(j + 2));
        const float t2 = fmaxf(2.0f - r, 0.0f);
        const float t1 = fmaxf(1.0f - r, 0.0f);
        b[j] = (t2 * t2 * t2 - 4.0f * t1 * t1 * t1) * (1.0f / 6.0f);
    }
    // RBF via two-sided exp-ratio chains (4 expf)
    const float xh = (xn + 1.5f) * (7.0f / 3.0f);
    const float C2 = 0.13533528f;   // e^-2
    float rb[8];
    {
        float gl = __expf(-xh * xh);
        float fl = __expf(2.0f * xh - 1.0f);
        #pragma unroll
        for (int j = 0; j < 8; j++) { rb[j] = gl; gl *= fl; fl *= C2; }
        float gr = __expf(-(xh - 7.0f) * (xh - 7.0f));
        float fr = __expf(13.0f - 2.0f * xh);
        #pragma unroll
        for (int j = 7; j >= 0; j--) { rb[j] = fmaxf(rb[j], gr); gr *= fr; fr *= C2; }
    }
    feat[0] = fmaxf(xn, 0.0f);
    #pragma unroll
    for (int j = 0; j < NB; j++) feat[1 + j] = b[j] + rb[j];
}

// ---------------------------------------------------------------------------
// Kernel 1: warp-per-token LayerNorm + features (no smem, no __syncthreads)
// 256 threads = 8 warps = 8 tokens per block; lane owns 16 dims as 4 float4s.
// ---------------------------------------------------------------------------
__global__ __launch_bounds__(256)
void feat_kernel(const float* __restrict__ x,
                 const float* __restrict__ gamma_,
                 const float* __restrict__ beta_)
{
    const int warp = threadIdx.x >> 5;
    const int l    = threadIdx.x & 31;
    const int tok  = blockIdx.x * 8 + warp;

    const float4* xr = reinterpret_cast<const float4*>(x + (size_t)tok * DIN);
    const float4* g4 = reinterpret_cast<const float4*>(gamma_);
    const float4* b4 = reinterpret_cast<const float4*>(beta_);

    float4 v[4];
    float s1 = 0.0f, s2 = 0.0f;
    #pragma unroll
    for (int i = 0; i < 4; i++) {
        v[i] = xr[l + 32 * i];
        s1 += v[i].x + v[i].y + v[i].z + v[i].w;
        s2 += v[i].x * v[i].x + v[i].y * v[i].y + v[i].z * v[i].z + v[i].w * v[i].w;
    }
    #pragma unroll
    for (int o = 16; o > 0; o >>= 1) {
        s1 += __shfl_xor_sync(0xffffffffu, s1, o);
        s2 += __shfl_xor_sync(0xffffffffu, s2, o);
    }
    const float mu   = s1 * (1.0f / DIN);
    const float var  = s2 * (1.0f / DIN) - mu * mu;
    const float rstd = rsqrtf(var + 1e-5f);

    unsigned short* row = g_F + (size_t)tok * KR;

    #pragma unroll
    for (int i = 0; i < 4; i++) {
        const float4 gg = g4[l + 32 * i];
        const float4 bb = b4[l + 32 * i];
        const float xns[4] = {
            (v[i].x - mu) * rstd * gg.x + bb.x,
            (v[i].y - mu) * rstd * gg.y + bb.y,
            (v[i].z - mu) * rstd * gg.z + bb.z,
            (v[i].w - mu) * rstd * gg.w + bb.w
        };
        float f[4][9];
        #pragma unroll
        for (int c = 0; c < 4; c++) features_of(xns[c], f[c]);

        const int dbase = 128 * i + 4 * l;        // dims dbase..dbase+3
        #pragma unroll
        for (int j = 0; j < 9; j++) {
            ushort4 o4;
            o4.x = __half_as_ushort(__float2half_rn(f[0][j]));
            o4.y = __half_as_ushort(__float2half_rn(f[1][j]));
            o4.z = __half_as_ushort(__float2half_rn(f[2][j]));
            o4.w = __half_as_ushort(__float2half_rn(f[3][j]));
            *reinterpret_cast<ushort4*>(&row[j * 512 + dbase]) = o4;
        }
    }
}

// ---------------------------------------------------------------------------
// Kernel 2: pack weights -> fp16 B [o][j*512+d]
// ---------------------------------------------------------------------------
__global__ void pack_kernel(const float* __restrict__ bw,
                            const float* __restrict__ sw)
{
    const int idx = blockIdx.x * blockDim.x + threadIdx.x;
    if (idx >= 512 * KR) return;
    const int o = idx / KR;
    const int k = idx % KR;
    const int j = k >> 9;
    const int d = k & 511;
    const float w = (j == 0) ? bw[(size_t)o * DIN + d]
                             : sw[(size_t)o * (DIN * NB) + d * NB + (j - 1)];
    g_W[idx] = __half_as_ushort(__float2half_rn(w));
}

// ---------------------------------------------------------------------------
// Kernel 3: fp16 mma.sync GEMM  C[16384][512] = A[16384][4608] * B^T
// R10-proven config: CTA 256x128, 512 threads, 16 warps (4M x 4N) of 64x32,
// BK=64 SW128, 4-stage cp.async, single-buffered frags (128 regs = full RF).
// ---------------------------------------------------------------------------
__global__ __launch_bounds__(512, 1)
void gemm_kernel(float* __restrict__ C)
{
    extern __shared__ char smem_raw[];
    uint32_t raw;
    asm("{ .reg .u64 t; cvta.to.shared.u64 t, %1; cvt.u32.u64 %0, t; }"
        : "=r"(raw) : "l"(smem_raw));
    const uint32_t base = (raw + 1023) & ~1023u;

    const int tid  = threadIdx.x;
    const int wid  = tid >> 5;
    const int lane = tid & 31;
    const int wm   = wid & 3;          // 0..3 along M (64 each)
    const int wn   = wid >> 2;         // 0..3 along N (32 each)
    const int bm   = blockIdx.y * CTA_M;
    const int bn   = blockIdx.x * CTA_N;

    const int ld_r0 = tid >> 3;        // 0..63
    const int ld_c  = tid & 7;

    const int rx  = lane & 7;
    const int hiA = lane >> 4;
    const int hiB = (lane >> 3) & 1;
    uint32_t aoff[4], boff[2];
    #pragma unroll
    for (int mt = 0; mt < 4; mt++)
        aoff[mt] = (uint32_t)(wm * 64 + mt * 16 + (lane & 15)) * 128u;
    #pragma unroll
    for (int pp = 0; pp < 2; pp++)
        boff[pp] = 32768u + (uint32_t)(wn * 32 + pp * 16 + (lane & 7) + ((lane >> 4) << 3)) * 128u;

    float acc[4][4][4];
    #pragma unroll
    for (int mt = 0; mt < 4; mt++)
        #pragma unroll
        for (int nt = 0; nt < 4; nt++)
            #pragma unroll
            for (int q = 0; q < 4; q++) acc[mt][nt][q] = 0.0f;

    uint32_t fa[4][4], fb[2][4];

    #define LOAD_STAGE(sidx, SBASE) do {                                        \
        const int ko_ = (sidx) * BK;                                            \
        _Pragma("unroll")                                                       \
        for (int i_ = 0; i_ < 4; i_++) {                                        \
            const int r_ = ld_r0 + i_ * 64;                                     \
            cpa16((SBASE) + r_ * 128 + ((ld_c ^ (r_ & 7)) << 4),                \
                  g_F + (size_t)(bm + r_) * KR + ko_ + ld_c * 8);               \
        }                                                                       \
        _Pragma("unroll")                                                       \
        for (int i_ = 0; i_ < 2; i_++) {                                        \
            const int r_ = ld_r0 + i_ * 64;                                     \
            cpa16((SBASE) + 32768u + r_ * 128 + ((ld_c ^ (r_ & 7)) << 4),       \
                  g_W + (size_t)(bn + r_) * KR + ko_ + ld_c * 8);               \
        }                                                                       \
    } while (0)

    #define STEP(sv, BUF) do {                                                  \
        const int s_ = (sv);                                                    \
        asm volatile("cp.async.wait_group 2;" ::: "memory");                    \
        __syncthreads();                                                        \
        const uint32_t SA_ = base + (uint32_t)(BUF) * STAGE_BYTES;              \
        if (s_ + 3 < NST) {                                                     \
            LOAD_STAGE(s_ + 3, base + (uint32_t)(((BUF) + 3) & 3) * STAGE_BYTES); \
        }                                                                       \
        asm volatile("cp.async.commit_group;" ::: "memory");                    \
        _Pragma("unroll")                                                       \
        for (int ks_ = 0; ks_ < 4; ks_++) {                                     \
            _Pragma("unroll")                                                   \
            for (int mt_ = 0; mt_ < 4; mt_++)                                   \
                ldsm_x4(fa[mt_], SA_ + aoff[mt_] +                              \
                        ((uint32_t)(((ks_ << 1) | hiA) ^ rx) << 4));            \
            _Pragma("unroll")                                                   \
            for (int pp_ = 0; pp_ < 2; pp_++)                                   \
                ldsm_x4(fb[pp_], SA_ + boff[pp_] +                              \
                        ((uint32_t)(((ks_ << 1) | hiB) ^ rx) << 4));            \
            _Pragma("unroll")                                                   \
            for (int mt_ = 0; mt_ < 4; mt_++)                                   \
                _Pragma("unroll")                                               \
                for (int nt_ = 0; nt_ < 4; nt_++) {                             \
                    const uint32_t b0_ = (nt_ & 1) ? fb[nt_ >> 1][2] : fb[nt_ >> 1][0]; \
                    const uint32_t b1_ = (nt_ & 1) ? fb[nt_ >> 1][3] : fb[nt_ >> 1][1]; \
                    mma_f16_f32(acc[mt_][nt_], fa[mt_], b0_, b1_);              \
                }                                                               \
        }                                                                       \
    } while (0)

    // prologue: stages 0..2 into bufs 0..2
    LOAD_STAGE(0, base);
    asm volatile("cp.async.commit_group;" ::: "memory");
    LOAD_STAGE(1, base + STAGE_BYTES);
    asm volatile("cp.async.commit_group;" ::: "memory");
    LOAD_STAGE(2, base + 2 * STAGE_BYTES);
    asm volatile("cp.async.commit_group;" ::: "memory");

    for (int t = 0; t < NST; t += 4) {
        STEP(t + 0, 0);
        STEP(t + 1, 1);
        STEP(t + 2, 2);
        STEP(t + 3, 3);
    }

    // epilogue: thread holds rows g, g+8 and cols 2tg, 2tg+1 per (mt, nt)
    const int g  = lane >> 2;
    const int tg = lane & 3;
    #pragma unroll
    for (int mt = 0; mt < 4; mt++) {
        const int row0 = bm + wm * 64 + mt * 16 + g;
        #pragma unroll
        for (int nt = 0; nt < 4; nt++) {
            const int col = bn + wn * 32 + nt * 8 + tg * 2;
            float2 v0; v0.x = acc[mt][nt][0]; v0.y = acc[mt][nt][1];
            float2 v1; v1.x = acc[mt][nt][2]; v1.y = acc[mt][nt][3];
            *(float2*)&C[(size_t)row0 * 512 + col]       = v0;
            *(float2*)&C[(size_t)(row0 + 8) * 512 + col] = v1;
        }
    }
}

// ---------------------------------------------------------------------------
extern "C" void kernel_launch(void* const* d_in, const int* in_sizes, int n_in,
                              void* d_out, int out_size)
{
    const float* x  = (const float*)d_in[0];
    const float* g  = (const float*)d_in[1];
    const float* bt = (const float*)d_in[2];
    const float* bw = (const float*)d_in[3];
    const float* sw = (const float*)d_in[4];
    float* out = (float*)d_out;

    const int SMEM_DYN = 1024 + 4 * STAGE_BYTES;
    cudaFuncSetAttribute(gemm_kernel, cudaFuncAttributeMaxDynamicSharedMemorySize, SMEM_DYN);

    feat_kernel<<<NTOK / 8, 256>>>(x, g, bt);
    pack_kernel<<<(512 * KR + 255) / 256, 256>>>(bw, sw);
    gemm_kernel<<<dim3(512 / CTA_N, NTOK / CTA_M), 512, SMEM_DYN>>>(out);
}

// round 14
// speedup vs baseline: 1.4541x; 1.0093x over previous
#include <cuda_runtime.h>
#include <cuda_bf16.h>
#include <cuda_fp16.h>
#include <cstdint>

#define NTOK 16384
#define DIN  512
#define NB   8
#define KR   4608                 // K = 512*9, single fp16 term
#define BK   64                   // K per stage = 128 bytes/row
#define NST  72                   // KR / BK (divisible by 4)
#define STAGE_BYTES 49152         // A 32KB + B 16KB
#define CTA_M 256
#define CTA_N 128
#define FEAT_BLOCKS (NTOK / 8)    // 2048
#define PACK_BLOCKS ((512 * KR) / 256)  // 9216

// Scratch (allocation-free), fp16 payloads
__device__ __align__(16) unsigned short g_F[(size_t)NTOK * KR];
__device__ __align__(16) unsigned short g_W[(size_t)512 * KR];

__device__ __forceinline__ void cpa16(uint32_t dst, const void* src) {
    asm volatile("cp.async.cg.shared.global [%0], [%1], 16;" :: "r"(dst), "l"(src));
}
__device__ __forceinline__ void ldsm_x4(uint32_t* r, uint32_t addr) {
    asm volatile("ldmatrix.sync.aligned.m8n8.x4.shared.b16 {%0,%1,%2,%3}, [%4];"
                 : "=r"(r[0]), "=r"(r[1]), "=r"(r[2]), "=r"(r[3]) : "r"(addr));
}
__device__ __forceinline__ void mma_f16_f32(float* c, const uint32_t* a,
                                            uint32_t b0, uint32_t b1) {
    asm volatile("mma.sync.aligned.m16n8k16.row.col.f32.f16.f16.f32 "
                 "{%0,%1,%2,%3}, {%4,%5,%6,%7}, {%8,%9}, {%0,%1,%2,%3};"
                 : "+f"(c[0]), "+f"(c[1]), "+f"(c[2]), "+f"(c[3])
                 : "r"(a[0]), "r"(a[1]), "r"(a[2]), "r"(a[3]), "r"(b0), "r"(b1));
}

// ---------------------------------------------------------------------------
// per-dim feature vector from normalized activation xn
// ---------------------------------------------------------------------------
__device__ __forceinline__ void features_of(float xn, float* feat) {
    // cubic B-spline via closed-form symmetric kernel
    const float p = (xn + 3.3f) * (1.0f / 0.6f);
    float b[8];
    #pragma unroll
    for (int j = 0; j < 8; j++) {
        const float r  = fabsf(p - (float)(j + 2));
        const float t2 = fmaxf(2.0f - r, 0.0f);
        const float t1 = fmaxf(1.0f - r, 0.0f);
        b[j] = (t2 * t2 * t2 - 4.0f * t1 * t1 * t1) * (1.0f / 6.0f);
    }
    // RBF direct: one MUFU per center (MUFU pipe is otherwise idle)
    const float xh = (xn + 1.5f) * (7.0f / 3.0f);
    feat[0] = fmaxf(xn, 0.0f);
    #pragma unroll
    for (int j = 0; j < NB; j++) {
        const float u = xh - (float)j;
        feat[1 + j] = b[j] + __expf(-u * u);
    }
}

// ---------------------------------------------------------------------------
// Fused kernel 1+2: blocks [0, FEAT_BLOCKS) do warp-per-token LayerNorm +
// features; blocks [FEAT_BLOCKS, FEAT_BLOCKS+PACK_BLOCKS) pack weights.
// ---------------------------------------------------------------------------
__global__ __launch_bounds__(256)
void feat_pack_kernel(const float* __restrict__ x,
                      const float* __restrict__ gamma_,
                      const float* __restrict__ beta_,
                      const float* __restrict__ bw,
                      const float* __restrict__ sw)
{
    if (blockIdx.x >= FEAT_BLOCKS) {
        // ---- pack: fp16 B [o][j*512+d] ----
        const int idx = (blockIdx.x - FEAT_BLOCKS) * 256 + threadIdx.x;
        const int o = idx / KR;
        const int k = idx % KR;
        const int j = k >> 9;
        const int d = k & 511;
        const float w = (j == 0) ? bw[(size_t)o * DIN + d]
                                 : sw[(size_t)o * (DIN * NB) + d * NB + (j - 1)];
        g_W[idx] = __half_as_ushort(__float2half_rn(w));
        return;
    }

    // ---- feat: warp-per-token, no smem, no __syncthreads ----
    const int warp = threadIdx.x >> 5;
    const int l    = threadIdx.x & 31;
    const int tok  = blockIdx.x * 8 + warp;

    const float4* xr = reinterpret_cast<const float4*>(x + (size_t)tok * DIN);
    const float4* g4 = reinterpret_cast<const float4*>(gamma_);
    const float4* b4 = reinterpret_cast<const float4*>(beta_);

    float4 v[4];
    float s1 = 0.0f, s2 = 0.0f;
    #pragma unroll
    for (int i = 0; i < 4; i++) {
        v[i] = xr[l + 32 * i];
        s1 += v[i].x + v[i].y + v[i].z + v[i].w;
        s2 += v[i].x * v[i].x + v[i].y * v[i].y + v[i].z * v[i].z + v[i].w * v[i].w;
    }
    #pragma unroll
    for (int o = 16; o > 0; o >>= 1) {
        s1 += __shfl_xor_sync(0xffffffffu, s1, o);
        s2 += __shfl_xor_sync(0xffffffffu, s2, o);
    }
    const float mu   = s1 * (1.0f / DIN);
    const float var  = s2 * (1.0f / DIN) - mu * mu;
    const float rstd = rsqrtf(var + 1e-5f);

    unsigned short* row = g_F + (size_t)tok * KR;

    #pragma unroll
    for (int i = 0; i < 4; i++) {
        const float4 gg = g4[l + 32 * i];
        const float4 bb = b4[l + 32 * i];
        const float xns[4] = {
            (v[i].x - mu) * rstd * gg.x + bb.x,
            (v[i].y - mu) * rstd * gg.y + bb.y,
            (v[i].z - mu) * rstd * gg.z + bb.z,
            (v[i].w - mu) * rstd * gg.w + bb.w
        };
        float f[4][9];
        #pragma unroll
        for (int c = 0; c < 4; c++) features_of(xns[c], f[c]);

        const int dbase = 128 * i + 4 * l;        // dims dbase..dbase+3
        #pragma unroll
        for (int j = 0; j < 9; j++) {
            ushort4 o4;
            o4.x = __half_as_ushort(__float2half_rn(f[0][j]));
            o4.y = __half_as_ushort(__float2half_rn(f[1][j]));
            o4.z = __half_as_ushort(__float2half_rn(f[2][j]));
            o4.w = __half_as_ushort(__float2half_rn(f[3][j]));
            *reinterpret_cast<ushort4*>(&row[j * 512 + dbase]) = o4;
        }
    }
}

// ---------------------------------------------------------------------------
// Kernel 3: fp16 mma.sync GEMM  C[16384][512] = A[16384][4608] * B^T
// R10-proven config: CTA 256x128, 512 threads, 16 warps (4M x 4N) of 64x32,
// BK=64 SW128, 4-stage cp.async, single-buffered frags (128 regs = full RF).
// ---------------------------------------------------------------------------
__global__ __launch_bounds__(512, 1)
void gemm_kernel(float* __restrict__ C)
{
    extern __shared__ char smem_raw[];
    uint32_t raw;
    asm("{ .reg .u64 t; cvta.to.shared.u64 t, %1; cvt.u32.u64 %0, t; }"
        : "=r"(raw) : "l"(smem_raw));
    const uint32_t base = (raw + 1023) & ~1023u;

    const int tid  = threadIdx.x;
    const int wid  = tid >> 5;
    const int lane = tid & 31;
    const int wm   = wid & 3;          // 0..3 along M (64 each)
    const int wn   = wid >> 2;         // 0..3 along N (32 each)
    const int bm   = blockIdx.y * CTA_M;
    const int bn   = blockIdx.x * CTA_N;

    const int ld_r0 = tid >> 3;        // 0..63
    const int ld_c  = tid & 7;

    const int rx  = lane & 7;
    const int hiA = lane >> 4;
    const int hiB = (lane >> 3) & 1;
    uint32_t aoff[4], boff[2];
    #pragma unroll
    for (int mt = 0; mt < 4; mt++)
        aoff[mt] = (uint32_t)(wm * 64 + mt * 16 + (lane & 15)) * 128u;
    #pragma unroll
    for (int pp = 0; pp < 2; pp++)
        boff[pp] = 32768u + (uint32_t)(wn * 32 + pp * 16 + (lane & 7) + ((lane >> 4) << 3)) * 128u;

    float acc[4][4][4];
    #pragma unroll
    for (int mt = 0; mt < 4; mt++)
        #pragma unroll
        for (int nt = 0; nt < 4; nt++)
            #pragma unroll
            for (int q = 0; q < 4; q++) acc[mt][nt][q] = 0.0f;

    uint32_t fa[4][4], fb[2][4];

    #define LOAD_STAGE(sidx, SBASE) do {                                        \
        const int ko_ = (sidx) * BK;                                            \
        _Pragma("unroll")                                                       \
        for (int i_ = 0; i_ < 4; i_++) {                                        \
            const int r_ = ld_r0 + i_ * 64;                                     \
            cpa16((SBASE) + r_ * 128 + ((ld_c ^ (r_ & 7)) << 4),                \
                  g_F + (size_t)(bm + r_) * KR + ko_ + ld_c * 8);               \
        }                                                                       \
        _Pragma("unroll")                                                       \
        for (int i_ = 0; i_ < 2; i_++) {                                        \
            const int r_ = ld_r0 + i_ * 64;                                     \
            cpa16((SBASE) + 32768u + r_ * 128 + ((ld_c ^ (r_ & 7)) << 4),       \
                  g_W + (size_t)(bn + r_) * KR + ko_ + ld_c * 8);               \
        }                                                                       \
    } while (0)

    #define STEP(sv, BUF) do {                                                  \
        const int s_ = (sv);                                                    \
        asm volatile("cp.async.wait_group 2;" ::: "memory");                    \
        __syncthreads();                                                        \
        const uint32_t SA_ = base + (uint32_t)(BUF) * STAGE_BYTES;              \
        if (s_ + 3 < NST) {                                                     \
            LOAD_STAGE(s_ + 3, base + (uint32_t)(((BUF) + 3) & 3) * STAGE_BYTES); \
        }                                                                       \
        asm volatile("cp.async.commit_group;" ::: "memory");                    \
        _Pragma("unroll")                                                       \
        for (int ks_ = 0; ks_ < 4; ks_++) {                                     \
            _Pragma("unroll")                                                   \
            for (int mt_ = 0; mt_ < 4; mt_++)                                   \
                ldsm_x4(fa[mt_], SA_ + aoff[mt_] +                              \
                        ((uint32_t)(((ks_ << 1) | hiA) ^ rx) << 4));            \
            _Pragma("unroll")                                                   \
            for (int pp_ = 0; pp_ < 2; pp_++)                                   \
                ldsm_x4(fb[pp_], SA_ + boff[pp_] +                              \
                        ((uint32_t)(((ks_ << 1) | hiB) ^ rx) << 4));            \
            _Pragma("unroll")                                                   \
            for (int mt_ = 0; mt_ < 4; mt_++)                                   \
                _Pragma("unroll")                                               \
                for (int nt_ = 0; nt_ < 4; nt_++) {                             \
                    const uint32_t b0_ = (nt_ & 1) ? fb[nt_ >> 1][2] : fb[nt_ >> 1][0]; \
                    const uint32_t b1_ = (nt_ & 1) ? fb[nt_ >> 1][3] : fb[nt_ >> 1][1]; \
                    mma_f16_f32(acc[mt_][nt_], fa[mt_], b0_, b1_);              \
                }                                                               \
        }                                                                       \
    } while (0)

    // prologue: stages 0..2 into bufs 0..2
    LOAD_STAGE(0, base);
    asm volatile("cp.async.commit_group;" ::: "memory");
    LOAD_STAGE(1, base + STAGE_BYTES);
    asm volatile("cp.async.commit_group;" ::: "memory");
    LOAD_STAGE(2, base + 2 * STAGE_BYTES);
    asm volatile("cp.async.commit_group;" ::: "memory");

    for (int t = 0; t < NST; t += 4) {
        STEP(t + 0, 0);
        STEP(t + 1, 1);
        STEP(t + 2, 2);
        STEP(t + 3, 3);
    }

    // epilogue: thread holds rows g, g+8 and cols 2tg, 2tg+1 per (mt, nt)
    const int g  = lane >> 2;
    const int tg = lane & 3;
    #pragma unroll
    for (int mt = 0; mt < 4; mt++) {
        const int row0 = bm + wm * 64 + mt * 16 + g;
        #pragma unroll
        for (int nt = 0; nt < 4; nt++) {
            const int col = bn + wn * 32 + nt * 8 + tg * 2;
            float2 v0; v0.x = acc[mt][nt][0]; v0.y = acc[mt][nt][1];
            float2 v1; v1.x = acc[mt][nt][2]; v1.y = acc[mt][nt][3];
            *(float2*)&C[(size_t)row0 * 512 + col]       = v0;
            *(float2*)&C[(size_t)(row0 + 8) * 512 + col] = v1;
        }
    }
}

// ---------------------------------------------------------------------------
extern "C" void kernel_launch(void* const* d_in, const int* in_sizes, int n_in,
                              void* d_out, int out_size)
{
    const float* x  = (const float*)d_in[0];
    const float* g  = (const float*)d_in[1];
    const float* bt = (const float*)d_in[2];
    const float* bw = (const float*)d_in[3];
    const float* sw = (const float*)d_in[4];
    float* out = (float*)d_out;

    const int SMEM_DYN = 1024 + 4 * STAGE_BYTES;
    cudaFuncSetAttribute(gemm_kernel, cudaFuncAttributeMaxDynamicSharedMemorySize, SMEM_DYN);

    feat_pack_kernel<<<FEAT_BLOCKS + PACK_BLOCKS, 256>>>(x, g, bt, bw, sw);
    gemm_kernel<<<dim3(512 / CTA_N, NTOK / CTA_M), 512, SMEM_DYN>>>(out);
}